// round 17
// baseline (speedup 1.0000x reference)
#include <cuda_runtime.h>
#include <cuda_bf16.h>
#include <math.h>
#include <stdint.h>

namespace {
constexpr int Bc = 4, Sc = 1024, Ec = 512, Hc = 8, DKc = 64;
constexpr int M_TOT = Bc * Sc;                    // 4096
constexpr size_t NI = (size_t)M_TOT * Ec;         // input plane elems
constexpr size_t NW = (size_t)Ec * Ec;            // weight plane elems
constexpr size_t NQ = (size_t)Bc * Hc * Sc * DKc; // head-split plane elems
}

// bf16 hi/lo planes (device globals: allocation-free per harness rules)
__device__ unsigned short g_Ih[3 * NI], g_Il[3 * NI];
__device__ unsigned short g_Wh[4 * NW], g_Wl[4 * NW];
__device__ unsigned short g_Qh[NQ], g_Ql[NQ];
__device__ unsigned short g_Kh[NQ], g_Kl[NQ];
__device__ unsigned short g_Vh[NQ], g_Vl[NQ];
__device__ unsigned short g_Xh[NI], g_Xl[NI];

// ---- HMMA helpers (base sm_103 — no arch-specific features) ----------------
__device__ __forceinline__ unsigned smem_u32(const void* p) {
    return (unsigned)__cvta_generic_to_shared(p);
}
__device__ __forceinline__ void ldsm4(unsigned* r, unsigned addr) {
    asm volatile("ldmatrix.sync.aligned.m8n8.x4.shared.b16 {%0,%1,%2,%3}, [%4];"
                 : "=r"(r[0]), "=r"(r[1]), "=r"(r[2]), "=r"(r[3]) : "r"(addr));
}
__device__ __forceinline__ void ldsm4t(unsigned* r, unsigned addr) {
    asm volatile("ldmatrix.sync.aligned.m8n8.x4.trans.shared.b16 {%0,%1,%2,%3}, [%4];"
                 : "=r"(r[0]), "=r"(r[1]), "=r"(r[2]), "=r"(r[3]) : "r"(addr));
}
__device__ __forceinline__ void ldsm2(unsigned* r, unsigned addr) {
    asm volatile("ldmatrix.sync.aligned.m8n8.x2.shared.b16 {%0,%1}, [%2];"
                 : "=r"(r[0]), "=r"(r[1]) : "r"(addr));
}
__device__ __forceinline__ void hmma(float* c, const unsigned* a, const unsigned* b) {
    asm volatile(
        "mma.sync.aligned.m16n8k16.row.col.f32.bf16.bf16.f32 "
        "{%0,%1,%2,%3}, {%4,%5,%6,%7}, {%8,%9}, {%0,%1,%2,%3};"
        : "+f"(c[0]), "+f"(c[1]), "+f"(c[2]), "+f"(c[3])
        : "r"(a[0]), "r"(a[1]), "r"(a[2]), "r"(a[3]), "r"(b[0]), "r"(b[1]));
}
// bf16 hi/lo split of two floats, each packed as bf16x2 words
__device__ __forceinline__ void split2(float a, float b, unsigned& hi, unsigned& lo) {
    __nv_bfloat16 ha = __float2bfloat16_rn(a), hb = __float2bfloat16_rn(b);
    __nv_bfloat16 la = __float2bfloat16_rn(a - __bfloat162float(ha));
    __nv_bfloat16 lb = __float2bfloat16_rn(b - __bfloat162float(hb));
    __nv_bfloat162 h2{ha, hb}, l2{la, lb};
    hi = *(unsigned*)&h2;
    lo = *(unsigned*)&l2;
}
// pack two f32 -> bf16x2 (lo in low half)
__device__ __forceinline__ unsigned pk2(float lo, float hi) {
    unsigned r;
    asm("cvt.rn.bf16x2.f32 %0, %1, %2;" : "=r"(r) : "f"(hi), "f"(lo));
    return r;
}

// ---------------------------------------------------------------------------
// Prep: split f32 tensors into bf16 hi/lo planes. z: 0..2 inputs, 3..6 weights.
// ---------------------------------------------------------------------------
__global__ void __launch_bounds__(256) prep_split(
    const float* __restrict__ q, const float* __restrict__ k,
    const float* __restrict__ v, const float* __restrict__ wq,
    const float* __restrict__ wk, const float* __restrict__ wv,
    const float* __restrict__ wo, unsigned short* __restrict__ Ih,
    unsigned short* __restrict__ Il, unsigned short* __restrict__ Wh,
    unsigned short* __restrict__ Wl) {
    const int z = blockIdx.z;
    const float* src;
    unsigned short *dh, *dl;
    size_t n;
    if (z < 3) {
        src = (z == 0) ? q : (z == 1) ? k : v;
        dh = Ih + (size_t)z * NI;
        dl = Il + (size_t)z * NI;
        n = NI;
    } else {
        const int w = z - 3;
        src = (w == 0) ? wq : (w == 1) ? wk : (w == 2) ? wv : wo;
        dh = Wh + (size_t)w * NW;
        dl = Wl + (size_t)w * NW;
        n = NW;
    }
    const size_t i4 = ((size_t)blockIdx.x * 256 + threadIdx.x) * 4;
    if (i4 >= n) return;
    float4 val = *(const float4*)&src[i4];
    unsigned h01, l01, h23, l23;
    split2(val.x, val.y, h01, l01);
    split2(val.z, val.w, h23, l23);
    *(uint2*)&dh[i4] = make_uint2(h01, h23);
    *(uint2*)&dl[i4] = make_uint2(l01, l23);
}

// ---------------------------------------------------------------------------
// HMMA GEMM: Y = X * W^T + bias via bf16x3 split, copy-only staging from
// pre-split planes. Tile 128m x 64n, BK=64, 8 warps 2x4, warp 64m x 16n.
// SPLIT=true: write Y as bf16 hi/lo planes in [B,H,S,DK]; else f32 [M,E].
// Smem: Xhi 16K | Xlo 16K | Whi 8K | Wlo 8K = 48 KB.
// ---------------------------------------------------------------------------
template <bool SPLIT>
__device__ __forceinline__ void tgemm_body(
    const unsigned short* __restrict__ Xh, const unsigned short* __restrict__ Xl,
    const unsigned short* __restrict__ Wh, const unsigned short* __restrict__ Wl,
    const float* __restrict__ bias, float* __restrict__ Yf,
    unsigned short* __restrict__ Yh, unsigned short* __restrict__ Yl) {
    extern __shared__ char sb[];
    char* Xhi = sb;
    char* Xlo = sb + 16384;
    char* Whi = sb + 32768;
    char* Wlo = sb + 40960;
    const unsigned sXh = smem_u32(Xhi), sXl = smem_u32(Xlo);
    const unsigned sWh = smem_u32(Whi), sWl = smem_u32(Wlo);

    const int tid = threadIdx.x, warp = tid >> 5, lane = tid & 31;
    const int wm = warp >> 2;
    const int wn = warp & 3;
    const int bm = blockIdx.y * 128, bn = blockIdx.x * 64;

    const int a_r = lane & 15;
    const int a_cs = (lane >> 4) << 4;
    const int b_r = lane & 7;
    const int b_cs = ((lane >> 3) & 1) << 4;

    float acc[4][2][4] = {};

    for (int ks = 0; ks < Ec / 64; ks++) {
        const int k0 = ks * 64;
        // X: 128 rows x (8 hi + 8 lo) 16B chunks = 2048
#pragma unroll
        for (int t = 0; t < 8; t++) {
            int idx = t * 256 + tid;
            int r = idx >> 4, cc = idx & 15;
            const unsigned short* srcp =
                ((cc < 8) ? Xh : Xl) + (size_t)(bm + r) * Ec + k0 + (cc & 7) * 8;
            char* dstb = (cc < 8) ? Xhi : Xlo;
            unsigned off = r * 128 + ((((cc & 7) * 16)) ^ ((r & 7) << 4));
            *(uint4*)(dstb + off) = *(const uint4*)srcp;
        }
        // W: 64 rows x 16 chunks = 1024
#pragma unroll
        for (int t = 0; t < 4; t++) {
            int idx = t * 256 + tid;
            int r = idx >> 4, cc = idx & 15;
            const unsigned short* srcp =
                ((cc < 8) ? Wh : Wl) + (size_t)(bn + r) * Ec + k0 + (cc & 7) * 8;
            char* dstb = (cc < 8) ? Whi : Wlo;
            unsigned off = r * 128 + ((((cc & 7) * 16)) ^ ((r & 7) << 4));
            *(uint4*)(dstb + off) = *(const uint4*)srcp;
        }
        __syncthreads();

#pragma unroll
        for (int k = 0; k < 4; k++) {
            const int kb = k * 32;
            unsigned ah[4][4], al[4][4];
#pragma unroll
            for (int mt = 0; mt < 4; mt++) {
                const int row = wm * 64 + mt * 16 + a_r;
                const unsigned off = row * 128 + ((kb + a_cs) ^ ((row & 7) << 4));
                ldsm4(ah[mt], sXh + off);
                ldsm4(al[mt], sXl + off);
            }
            unsigned bh[2][2], bl[2][2];
#pragma unroll
            for (int nt = 0; nt < 2; nt++) {
                const int row = wn * 16 + nt * 8 + b_r;
                const unsigned off = row * 128 + ((kb + b_cs) ^ ((row & 7) << 4));
                ldsm2(bh[nt], sWh + off);
                ldsm2(bl[nt], sWl + off);
            }
#pragma unroll
            for (int mt = 0; mt < 4; mt++)
#pragma unroll
                for (int nt = 0; nt < 2; nt++) {
                    hmma(acc[mt][nt], ah[mt], bh[nt]);
                    hmma(acc[mt][nt], ah[mt], bl[nt]);
                    hmma(acc[mt][nt], al[mt], bh[nt]);
                }
        }
        __syncthreads();
    }

    const int lr = lane >> 2, lc = (lane & 3) << 1;
#pragma unroll
    for (int mt = 0; mt < 4; mt++)
#pragma unroll
        for (int nt = 0; nt < 2; nt++) {
            const int ncol = wn * 16 + nt * 8 + lc;
            const float2 bv = *(const float2*)&bias[bn + ncol];
            const int m0 = bm + wm * 64 + mt * 16 + lr;
#pragma unroll
            for (int half = 0; half < 2; half++) {
                const int m = m0 + half * 8;
                float2 v;
                v.x = acc[mt][nt][half * 2 + 0] + bv.x;
                v.y = acc[mt][nt][half * 2 + 1] + bv.y;
                if (SPLIT) {
                    const int bIdx = m >> 10, s = m & (Sc - 1);
                    const int h = bn >> 6, d = (bn + ncol) & 63;
                    const size_t eo =
                        (((size_t)bIdx * Hc + h) * Sc + s) * DKc + d;
                    unsigned hi, lo;
                    split2(v.x, v.y, hi, lo);
                    *(unsigned*)&Yh[eo] = hi;
                    *(unsigned*)&Yl[eo] = lo;
                } else {
                    *(float2*)&Yf[(size_t)m * Ec + bn + ncol] = v;
                }
            }
        }
}

__global__ void __launch_bounds__(256, 2) gemm_qkv(
    const unsigned short* __restrict__ Ih, const unsigned short* __restrict__ Il,
    const unsigned short* __restrict__ Wh, const unsigned short* __restrict__ Wl,
    const float* __restrict__ bq, const float* __restrict__ bk,
    const float* __restrict__ bv, unsigned short* __restrict__ Qh,
    unsigned short* __restrict__ Ql, unsigned short* __restrict__ Kh,
    unsigned short* __restrict__ Kl, unsigned short* __restrict__ Vh,
    unsigned short* __restrict__ Vl) {
    const int z = blockIdx.z;
    const float* b = (z == 0) ? bq : (z == 1) ? bk : bv;
    unsigned short* Yh = (z == 0) ? Qh : (z == 1) ? Kh : Vh;
    unsigned short* Yl = (z == 0) ? Ql : (z == 1) ? Kl : Vl;
    tgemm_body<true>(Ih + (size_t)z * NI, Il + (size_t)z * NI,
                     Wh + (size_t)z * NW, Wl + (size_t)z * NW, b, nullptr, Yh, Yl);
}

__global__ void __launch_bounds__(256, 2) gemm_out(
    const unsigned short* __restrict__ Xh, const unsigned short* __restrict__ Xl,
    const unsigned short* __restrict__ Wh, const unsigned short* __restrict__ Wl,
    const float* __restrict__ bias, float* __restrict__ Y) {
    tgemm_body<false>(Xh, Xl, Wh + 3 * NW, Wl + 3 * NW, bias, Y, nullptr, nullptr);
}

// ---------------------------------------------------------------------------
// FA2-style tensor-core attention (validated Round 13), copy-only staging
// from bf16 hi/lo planes; epilogue writes X hi/lo planes.
// Smem: Qhi 16K | Qlo 16K | Khi 8K | Klo 8K | Vhi 8K | Vlo 8K = 64 KB.
// ---------------------------------------------------------------------------
__global__ void __launch_bounds__(256, 2) attn_kernel(
    const unsigned short* __restrict__ Qhg, const unsigned short* __restrict__ Qlg,
    const unsigned short* __restrict__ Khg, const unsigned short* __restrict__ Klg,
    const unsigned short* __restrict__ Vhg, const unsigned short* __restrict__ Vlg,
    const float* __restrict__ dist, const int* __restrict__ mask,
    const float* __restrict__ cw1, const float* __restrict__ cb1,
    const float* __restrict__ cw2, const float* __restrict__ cb2,
    unsigned short* __restrict__ Xhg, unsigned short* __restrict__ Xlg) {
    extern __shared__ char sma[];
    char* Qh = sma;
    char* Ql = sma + 16384;
    char* Kh = sma + 32768;
    char* Kl = sma + 40960;
    char* Vh = sma + 49152;
    char* Vl = sma + 57344;
    const unsigned sQh = smem_u32(Qh), sQl = smem_u32(Ql);
    const unsigned sKh = smem_u32(Kh), sKl = smem_u32(Kl);
    const unsigned sVh = smem_u32(Vh), sVl = smem_u32(Vl);

    const int tid = threadIdx.x, warp = tid >> 5, lane = tid & 31;
    const int lr = lane >> 2, lc = lane & 3;
    const int b = blockIdx.z, h = blockIdx.y;
    const int q0 = blockIdx.x * 128;

    const size_t hb = ((size_t)b * Hc + h) * Sc * DKc;

    float w1[8], b1[8], w2[8];
#pragma unroll
    for (int t = 0; t < 8; t++) {
        w1[t] = cw1[t];
        b1[t] = cb1[t];
        w2[t] = cw2[h * Hc + t];
    }
    const float c2 = cb2[h];

    // stage Q tile 128x64 (hi/lo) — copy-only
#pragma unroll
    for (int t = 0; t < 8; t++) {
        int idx = t * 256 + tid;
        int r = idx >> 4, cc = idx & 15;
        const unsigned short* srcp =
            ((cc < 8) ? Qhg : Qlg) + hb + (size_t)(q0 + r) * DKc + (cc & 7) * 8;
        char* dstb = (cc < 8) ? Qh : Ql;
        unsigned off = r * 128 + ((((cc & 7) * 16)) ^ ((r & 7) << 4));
        *(uint4*)(dstb + off) = *(const uint4*)srcp;
    }

    float oacc[8][4] = {};
    float mrow0 = -INFINITY, mrow1 = -INFINITY, lrow0 = 0.f, lrow1 = 0.f;

    const int qi0 = q0 + warp * 16 + lr;
    const int qi1 = qi0 + 8;

    for (int k0 = 0; k0 < Sc; k0 += 64) {
        __syncthreads();  // prior PV reads of K/V done (also covers Q on iter 0)
        // stage K/V tiles 64x64 hi/lo: 4*512 chunks — copy-only
#pragma unroll
        for (int t = 0; t < 8; t++) {
            int idx = t * 256 + tid;
            int sel = idx >> 9, rem = idx & 511;
            int r = rem >> 3, c = rem & 7;
            const unsigned short* srcp =
                ((sel == 0) ? Khg : (sel == 1) ? Klg : (sel == 2) ? Vhg : Vlg) + hb +
                (size_t)(k0 + r) * DKc + c * 8;
            char* dstb = (sel == 0) ? Kh : (sel == 1) ? Kl : (sel == 2) ? Vh : Vl;
            unsigned off = r * 128 + ((c * 16) ^ ((r & 7) << 4));
            *(uint4*)(dstb + off) = *(const uint4*)srcp;
        }
        __syncthreads();

        // ---- S = Q K^T (3-split HMMA)
        float sacc[8][4] = {};
#pragma unroll
        for (int kk = 0; kk < 4; kk++) {
            const int kb = kk * 32;
            unsigned ah[4], al[4];
            {
                const int row = warp * 16 + (lane & 15);
                const unsigned off =
                    row * 128 + (((unsigned)(kb + ((lane >> 4) << 4))) ^ ((row & 7) << 4));
                ldsm4(ah, sQh + off);
                ldsm4(al, sQl + off);
            }
#pragma unroll
            for (int ntp = 0; ntp < 4; ntp++) {
                const int row = ntp * 16 + ((lane >> 4) << 3) + (lane & 7);
                const unsigned off =
                    row * 128 +
                    (((unsigned)(kb + (((lane >> 3) & 1) << 4))) ^ ((row & 7) << 4));
                unsigned bh[4], bl[4];
                ldsm4(bh, sKh + off);
                ldsm4(bl, sKl + off);
                hmma(sacc[2 * ntp], ah, &bh[0]);
                hmma(sacc[2 * ntp], ah, &bl[0]);
                hmma(sacc[2 * ntp], al, &bh[0]);
                hmma(sacc[2 * ntp + 1], ah, &bh[2]);
                hmma(sacc[2 * ntp + 1], ah, &bl[2]);
                hmma(sacc[2 * ntp + 1], al, &bh[2]);
            }
        }

        // ---- bias * scale, mask
        const size_t ro0 = ((size_t)b * Sc + qi0) * Sc + k0;
        const size_t ro1 = ((size_t)b * Sc + qi1) * Sc + k0;
#pragma unroll
        for (int nt = 0; nt < 8; nt++) {
            const int col = nt * 8 + lc * 2;
            float2 d0 = *(const float2*)&dist[ro0 + col];
            int2 m0 = *(const int2*)&mask[ro0 + col];
            float2 d1 = *(const float2*)&dist[ro1 + col];
            int2 m1 = *(const int2*)&mask[ro1 + col];
            float dd[4] = {d0.x, d0.y, d1.x, d1.y};
            int mm[4] = {m0.x, m0.y, m1.x, m1.y};
#pragma unroll
            for (int e = 0; e < 4; e++) {
                float bias = c2;
#pragma unroll
                for (int t = 0; t < 8; t++)
                    bias += w2[t] * fmaxf(fmaf(dd[e], w1[t], b1[t]), 0.f);
                float sv = sacc[nt][e] * 0.125f * bias;
                sacc[nt][e] = (mm[e] == 0) ? -1e9f : sv;
            }
        }

        // ---- online softmax (4-lane quad shares a row)
        float mx0 = sacc[0][0], mx1 = sacc[0][2];
#pragma unroll
        for (int nt = 0; nt < 8; nt++) {
            mx0 = fmaxf(mx0, fmaxf(sacc[nt][0], sacc[nt][1]));
            mx1 = fmaxf(mx1, fmaxf(sacc[nt][2], sacc[nt][3]));
        }
        mx0 = fmaxf(mx0, __shfl_xor_sync(0xffffffffu, mx0, 1));
        mx0 = fmaxf(mx0, __shfl_xor_sync(0xffffffffu, mx0, 2));
        mx1 = fmaxf(mx1, __shfl_xor_sync(0xffffffffu, mx1, 1));
        mx1 = fmaxf(mx1, __shfl_xor_sync(0xffffffffu, mx1, 2));
        const float mn0 = fmaxf(mrow0, mx0), mn1 = fmaxf(mrow1, mx1);
        const float al0 = __expf(mrow0 - mn0), al1 = __expf(mrow1 - mn1);
        mrow0 = mn0;
        mrow1 = mn1;
        float rs0 = 0.f, rs1 = 0.f;
#pragma unroll
        for (int nt = 0; nt < 8; nt++) {
            sacc[nt][0] = __expf(sacc[nt][0] - mn0);
            sacc[nt][1] = __expf(sacc[nt][1] - mn0);
            sacc[nt][2] = __expf(sacc[nt][2] - mn1);
            sacc[nt][3] = __expf(sacc[nt][3] - mn1);
            rs0 += sacc[nt][0] + sacc[nt][1];
            rs1 += sacc[nt][2] + sacc[nt][3];
        }
        rs0 += __shfl_xor_sync(0xffffffffu, rs0, 1);
        rs0 += __shfl_xor_sync(0xffffffffu, rs0, 2);
        rs1 += __shfl_xor_sync(0xffffffffu, rs1, 1);
        rs1 += __shfl_xor_sync(0xffffffffu, rs1, 2);
        lrow0 = lrow0 * al0 + rs0;
        lrow1 = lrow1 * al1 + rs1;
#pragma unroll
        for (int dt = 0; dt < 8; dt++) {
            oacc[dt][0] *= al0;
            oacc[dt][1] *= al0;
            oacc[dt][2] *= al1;
            oacc[dt][3] *= al1;
        }

        // ---- O += P V (3-split; P accum regs ARE the A fragments)
#pragma unroll
        for (int kk = 0; kk < 4; kk++) {
            unsigned Ah[4], Al[4];
#pragma unroll
            for (int half = 0; half < 2; half++) {
                const float p0 = sacc[2 * kk + half][0];
                const float p1 = sacc[2 * kk + half][1];
                const float p2 = sacc[2 * kk + half][2];
                const float p3 = sacc[2 * kk + half][3];
                unsigned ph01 = pk2(p0, p1);
                unsigned ph23 = pk2(p2, p3);
                float r0 = p0 - __uint_as_float(ph01 << 16);
                float r1 = p1 - __uint_as_float(ph01 & 0xFFFF0000u);
                float r2 = p2 - __uint_as_float(ph23 << 16);
                float r3 = p3 - __uint_as_float(ph23 & 0xFFFF0000u);
                Ah[2 * half] = ph01;
                Ah[2 * half + 1] = ph23;
                Al[2 * half] = pk2(r0, r1);
                Al[2 * half + 1] = pk2(r2, r3);
            }
#pragma unroll
            for (int dtp = 0; dtp < 4; dtp++) {
                const int row = kk * 16 + (lane & 15);
                const unsigned off =
                    row * 128 +
                    (((unsigned)(dtp * 32 + ((lane >> 4) << 4))) ^ ((row & 7) << 4));
                unsigned bhv[4], blv[4];
                ldsm4t(bhv, sVh + off);
                ldsm4t(blv, sVl + off);
                hmma(oacc[2 * dtp], Ah, &bhv[0]);
                hmma(oacc[2 * dtp], Ah, &blv[0]);
                hmma(oacc[2 * dtp], Al, &bhv[0]);
                hmma(oacc[2 * dtp + 1], Ah, &bhv[2]);
                hmma(oacc[2 * dtp + 1], Ah, &blv[2]);
                hmma(oacc[2 * dtp + 1], Al, &bhv[2]);
            }
        }
    }

    // epilogue: normalize, split, write X hi/lo planes in [B,S,E]
    const float inv0 = 1.f / lrow0, inv1 = 1.f / lrow1;
#pragma unroll
    for (int dt = 0; dt < 8; dt++) {
        const int col = h * DKc + dt * 8 + lc * 2;
        const size_t e0 = ((size_t)b * Sc + qi0) * Ec + col;
        const size_t e1 = ((size_t)b * Sc + qi1) * Ec + col;
        unsigned hi, lo;
        split2(oacc[dt][0] * inv0, oacc[dt][1] * inv0, hi, lo);
        *(unsigned*)&Xhg[e0] = hi;
        *(unsigned*)&Xlg[e0] = lo;
        split2(oacc[dt][2] * inv1, oacc[dt][3] * inv1, hi, lo);
        *(unsigned*)&Xhg[e1] = hi;
        *(unsigned*)&Xlg[e1] = lo;
    }
}

// ---------------------------------------------------------------------------

extern "C" void kernel_launch(void* const* d_in, const int* in_sizes, int n_in,
                              void* d_out, int out_size) {
    const float* query = (const float*)d_in[0];
    const float* key   = (const float*)d_in[1];
    const float* value = (const float*)d_in[2];
    const float* dist  = (const float*)d_in[3];
    const int*   mask  = (const int*)d_in[4];
    const float* Wq = (const float*)d_in[5];
    const float* bq = (const float*)d_in[6];
    const float* Wk = (const float*)d_in[7];
    const float* bk = (const float*)d_in[8];
    const float* Wv = (const float*)d_in[9];
    const float* bv = (const float*)d_in[10];
    const float* Wo = (const float*)d_in[11];
    const float* bo = (const float*)d_in[12];
    const float* cw1 = (const float*)d_in[13];
    const float* cb1 = (const float*)d_in[14];
    const float* cw2 = (const float*)d_in[15];
    const float* cb2 = (const float*)d_in[16];
    float* out = (float*)d_out;

    unsigned short *Ih, *Il, *Wh, *Wl, *Qh, *Ql, *Kh, *Kl, *Vh, *Vl, *Xh, *Xl;
    cudaGetSymbolAddress((void**)&Ih, g_Ih);
    cudaGetSymbolAddress((void**)&Il, g_Il);
    cudaGetSymbolAddress((void**)&Wh, g_Wh);
    cudaGetSymbolAddress((void**)&Wl, g_Wl);
    cudaGetSymbolAddress((void**)&Qh, g_Qh);
    cudaGetSymbolAddress((void**)&Ql, g_Ql);
    cudaGetSymbolAddress((void**)&Kh, g_Kh);
    cudaGetSymbolAddress((void**)&Kl, g_Kl);
    cudaGetSymbolAddress((void**)&Vh, g_Vh);
    cudaGetSymbolAddress((void**)&Vl, g_Vl);
    cudaGetSymbolAddress((void**)&Xh, g_Xh);
    cudaGetSymbolAddress((void**)&Xl, g_Xl);

    // prep: split inputs + weights once
    prep_split<<<dim3((unsigned)(NI / 1024), 1, 7), 256>>>(
        query, key, value, Wq, Wk, Wv, Wo, Ih, Il, Wh, Wl);

    const int gsmem = 49152;
    cudaFuncSetAttribute(gemm_qkv, cudaFuncAttributeMaxDynamicSharedMemorySize, gsmem);
    cudaFuncSetAttribute(gemm_out, cudaFuncAttributeMaxDynamicSharedMemorySize, gsmem);

    gemm_qkv<<<dim3(Ec / 64, M_TOT / 128, 3), 256, gsmem>>>(
        Ih, Il, Wh, Wl, bq, bk, bv, Qh, Ql, Kh, Kl, Vh, Vl);

    const int asmem = 65536;
    cudaFuncSetAttribute(attn_kernel, cudaFuncAttributeMaxDynamicSharedMemorySize, asmem);
    attn_kernel<<<dim3(Sc / 128, Hc, Bc), 256, asmem>>>(
        Qh, Ql, Kh, Kl, Vh, Vl, dist, mask, cw1, cb1, cw2, cb2, Xh, Xl);

    gemm_out<<<dim3(Ec / 64, M_TOT / 128, 1), 256, gsmem>>>(Xh, Xl, Wh, Wl, bo, out);
}